// round 11
// baseline (speedup 1.0000x reference)
#include <cuda_runtime.h>

// InterConv: B=2048, F=39, E=64, C=64, P=741
// out[b, c*P + p] = relu( U[c][ii[p]] + V[c][jj[p]] ),  U = x@Wi^T + bias, V = x@Wj^T
//
// Grid = 2*B: CTA = (batch b = bid>>1, c-set = {cbase..cbase+15} u {cbase+32..cbase+47},
// cbase = (bid&1)*16).  Interleaved set keeps (r, r+32) pairs co-resident so the
// phase-2 tab-window register cache (p0(r)==p0(r+32)) still works.
//
// 256 threads, 27.9 KB smem, <=51 regs -> 5 CTAs/SM (40 warps, L1D ~88 KB kept).
// smem (floats):
//   phase 0/1: xs [0,2624)   Wi [2624,4800)  Wj [4800,6976)   (rows stride 17 f4)
//   phase 2:   Uc [0,1312)   Vc [1312,2624)  tab [2624,3368)  (overlay, xs/W dead)

#define FN 39
#define EN 64
#define CN 64
#define PN 741            // 39*38/2
#define OUTB (CN * PN)    // 47424 floats per batch
#define THREADS 256

#define XS_OFF  0
#define WI_OFF  2624
#define WJ_OFF  4800
#define UC_OFF  0
#define VC_OFF  1312
#define TAB_OFF 2624
#define SMEM_FLOATS 6976
#define SMEM_BYTES  (SMEM_FLOATS * 4)   // 27904

// packed fp32x2 FMA (Blackwell; exact fp32 semantics, 2x FFMA throughput)
#define FMA_F32X2(acc, a, b) \
    asm("fma.rn.f32x2 %0, %1, %2, %0;" : "+l"(acc) : "l"(a), "l"(b))

extern __shared__ float smem[];

__global__ void __launch_bounds__(THREADS, 5)
interconv_kernel(const float* __restrict__ x,
                 const float* __restrict__ W,
                 const float* __restrict__ bias,
                 float* __restrict__ out)
{
    const int tid = threadIdx.x;
    const long long b = blockIdx.x >> 1;
    const int cbase = (blockIdx.x & 1) * 16;

    // local row l (0..31)  <->  global c(l) = cbase + (l&15) + (l>>4)*32

    // ---- Phase 0: stage x and this CTA's 32 W rows (float4) -------------
    {
        float4* xs4 = (float4*)(smem + XS_OFF);
        const float4* xb4 = (const float4*)(x + b * (long long)(FN * EN));
        #pragma unroll
        for (int it = 0; it < 3; it++) {
            int idx = tid + it * THREADS;
            if (idx < (FN * EN) / 4) xs4[idx] = xb4[idx];
        }
        if (tid < EN)                              // zero pad row f=39
            smem[XS_OFF + FN * EN + tid] = 0.f;

        // W gmem: [c][128] floats (k=0 -> Wi, k=1 -> Wj); local stride 17 f4
        float4* Wi4 = (float4*)(smem + WI_OFF);
        float4* Wj4 = (float4*)(smem + WJ_OFF);
        const float4* Wg4 = (const float4*)W;
        #pragma unroll
        for (int it = 0; it < 4; it++) {
            int idx = tid + it * THREADS;          // 1024 float4 total
            int l = idx >> 5, q = idx & 31;
            int cg = cbase + (l & 15) + ((l >> 4) << 5);
            float4 w = Wg4[cg * 32 + q];
            if (q < 16) Wi4[l * 17 + q] = w;
            else        Wj4[l * 17 + (q - 16)] = w;
        }
    }
    __syncthreads();

    // ---- Phase 1: U = x @ Wi^T + b, V = x @ Wj^T  (f32x2) ----------------
    const int cl = tid & 31;          // local row
    const int fg = tid >> 5;          // 0..7 (== warp id); f = fg + 8k, k<5
    const int cg = cbase + (cl & 15) + ((cl >> 4) << 5);

    unsigned long long au[5], av[5];
    #pragma unroll
    for (int k = 0; k < 5; k++) { au[k] = 0ull; av[k] = 0ull; }

    {
        const ulonglong2* xs2 = (const ulonglong2*)(smem + XS_OFF);   // [f][16]
        const ulonglong2* Wi2 = (const ulonglong2*)(smem + WI_OFF);   // [l][17]
        const ulonglong2* Wj2 = (const ulonglong2*)(smem + WJ_OFF);

        #pragma unroll
        for (int e4 = 0; e4 < 16; e4++) {
            ulonglong2 wi = Wi2[cl * 17 + e4];
            ulonglong2 wj = Wj2[cl * 17 + e4];
            #pragma unroll
            for (int k = 0; k < 5; k++) {
                ulonglong2 xv = xs2[(fg + 8 * k) * 16 + e4];  // f=39 row is zeros
                FMA_F32X2(au[k], xv.x, wi.x);
                FMA_F32X2(au[k], xv.y, wi.y);
                FMA_F32X2(av[k], xv.x, wj.x);
                FMA_F32X2(av[k], xv.y, wj.y);
            }
        }
    }
    __syncthreads();   // all xs/W reads done; safe to overlay

    // ---- Phase 1b: write Uc/Vc (transposed, stride 41) + build tab ------
    float* Uc = smem + UC_OFF;                // [l][41]
    float* Vc = smem + VC_OFF;                // [l][41]
    unsigned* tab = (unsigned*)(smem + TAB_OFF);

    {
        const float bc = __ldg(bias + cg);
        #pragma unroll
        for (int k = 0; k < 5; k++) {
            int f = fg + 8 * k;               // f<=39; f=39 lands in row pad
            float ulo = __uint_as_float((unsigned)au[k]);
            float uhi = __uint_as_float((unsigned)(au[k] >> 32));
            float vlo = __uint_as_float((unsigned)av[k]);
            float vhi = __uint_as_float((unsigned)(av[k] >> 32));
            Uc[cl * 41 + f] = ulo + uhi + bc; // bias folded into U
            Vc[cl * 41 + f] = vlo + vhi;
        }
        // pair table: np.triu_indices(F,1) row-major; byte offsets (i*4 | j*4<<16)
        for (int p = tid; p < PN; p += THREADS) {
            int i = 0, rem = p;
            while (rem >= FN - 1 - i) { rem -= FN - 1 - i; i++; }
            int j = i + 1 + rem;
            tab[p] = (unsigned)(i * 4) | ((unsigned)(j * 4) << 16);
        }
    }
    __syncthreads();

    // ---- Phase 2: expansion + relu, paired rows, register-cached tab -----
    // warp w owns m = 2w+k' (k'=0,1): rows l=m (gc=cbase+m) and l=16+m (gc+32).
    const int lane = tid & 31;
    const int wrp  = tid >> 5;
    float* outb = out + b * (long long)OUTB;

    #pragma unroll 1
    for (int kk = 0; kk < 2; kk++) {
        const int m   = wrp * 2 + kk;         // 0..15
        const int gc0 = cbase + m;
        const int p0  = (27 * gc0) & 31;      // == p0(gc0+32)

        // preload the 22-entry aligned tab window into registers
        unsigned tw[22];
        {
            const unsigned* tb = tab + p0 + lane;
            #pragma unroll
            for (int it = 0; it < 22; it++) tw[it] = tb[it * 32];
        }

        #pragma unroll
        for (int h = 0; h < 2; h++) {
            const int l  = m + 16 * h;
            const int gc = gc0 + 32 * h;
            const char* bu = (const char*)(Uc + l * 41);
            const char* bv = (const char*)(Vc + l * 41);
            float* po = outb + gc * PN;

            // head: p in [0, p0)
            if (lane < p0) {
                unsigned t = tab[lane];
                float u = *(const float*)(bu + (t & 0xFFFFu));
                float v = *(const float*)(bv + (t >> 16));
                __stcs(po + lane, fmaxf(u + v, 0.f));
            }

            // main: 22 full warp-iterations, register tab, 128B-aligned stores
            float* po2 = po + p0;
            #pragma unroll
            for (int it = 0; it < 22; it++) {
                unsigned t = tw[it];
                float u = *(const float*)(bu + (t & 0xFFFFu));
                float v = *(const float*)(bv + (t >> 16));
                __stcs(po2 + it * 32 + lane, fmaxf(u + v, 0.f));
            }

            // tail: p in [p0+704, 741)
            int p = p0 + 704 + lane;
            if (p < PN) {
                unsigned t = tab[p];
                float u = *(const float*)(bu + (t & 0xFFFFu));
                float v = *(const float*)(bv + (t >> 16));
                __stcs(po + p, fmaxf(u + v, 0.f));
            }
            p += 32;
            if (p < PN) {
                unsigned t = tab[p];
                float u = *(const float*)(bu + (t & 0xFFFFu));
                float v = *(const float*)(bv + (t >> 16));
                __stcs(po + p, fmaxf(u + v, 0.f));
            }
        }
    }
}

extern "C" void kernel_launch(void* const* d_in, const int* in_sizes, int n_in,
                              void* d_out, int out_size)
{
    const float* x    = (const float*)d_in[0];
    const float* W    = (const float*)d_in[1];
    const float* bias = (const float*)d_in[2];
    float* out = (float*)d_out;

    const int B = in_sizes[0] / (FN * EN);   // 2048

    cudaFuncSetAttribute(interconv_kernel,
                         cudaFuncAttributeMaxDynamicSharedMemorySize, SMEM_BYTES);
    interconv_kernel<<<B * 2, THREADS, SMEM_BYTES>>>(x, W, bias, out);
}

// round 12
// speedup vs baseline: 1.1587x; 1.1587x over previous
#include <cuda_runtime.h>

// InterConv: B=2048, F=39, E=64, C=64, P=741
// out[b, c*P + p] = relu( U[c][ii[p]] + V[c][jj[p]] ),  U = x@Wi^T + bias, V = x@Wj^T
//
// smem (floats), 48.3 KB -> 4 CTAs/SM:
//   phase 0/1: xs [0,2624)   Wi [2624,6976)  Wj [6976,11328)   (stride 68)
//   tab (dedicated, built in phase 0): [11328,12072)
//   phase 2 overlay: Uc [0,2624)  Vc [2624,5248)
//
// Phase 2: row-pairing (p0(c)=27c mod 32 == p0(c+32)); 22-entry tab window cached
// in registers per pair; both rows of a pair processed fused per iteration (2x ILP).

#define FN 39
#define EN 64
#define CN 64
#define PN 741            // 39*38/2
#define OUTB (CN * PN)    // 47424 floats per batch
#define THREADS 256

#define A_OFF   0
#define B_OFF   2624
#define TAB_OFF 11328
#define SMEM_FLOATS 12072
#define SMEM_BYTES  (SMEM_FLOATS * 4)   // 48288

// packed fp32x2 FMA (Blackwell; exact fp32 semantics, 2x FFMA throughput)
#define FMA_F32X2(acc, a, b) \
    asm("fma.rn.f32x2 %0, %1, %2, %0;" : "+l"(acc) : "l"(a), "l"(b))

extern __shared__ float smem[];

__global__ void __launch_bounds__(THREADS, 4)
interconv_kernel(const float* __restrict__ x,
                 const float* __restrict__ W,
                 const float* __restrict__ bias,
                 float* __restrict__ out)
{
    const int tid = threadIdx.x;
    const long long b = blockIdx.x;
    unsigned* tab = (unsigned*)(smem + TAB_OFF);

    // ---- Phase 0: stage x and W (float4); build tab behind LDG latency ---
    {
        float4* xs4 = (float4*)(smem + A_OFF);
        const float4* xb4 = (const float4*)(x + b * (long long)(FN * EN));
        #pragma unroll
        for (int it = 0; it < 3; it++) {
            int idx = tid + it * THREADS;
            if (idx < (FN * EN) / 4) xs4[idx] = xb4[idx];
        }
        if (tid < EN)                              // zero pad row f=39
            smem[A_OFF + FN * EN + tid] = 0.f;

        float4* Wi4 = (float4*)(smem + B_OFF);     // [c][17]
        float4* Wj4 = Wi4 + CN * 17;
        const float4* Wg4 = (const float4*)W;
        #pragma unroll
        for (int it = 0; it < 8; it++) {
            int idx = tid + it * THREADS;          // 2048 float4 total
            int c = idx >> 5, q = idx & 31;
            float4 w = Wg4[idx];
            if (q < 16) Wi4[c * 17 + q] = w;
            else        Wj4[c * 17 + (q - 16)] = w;
        }

        // pair table (np.triu_indices(F,1) row-major): byte offsets i*4 | j*4<<16.
        // Built here so the ALU hides behind the outstanding LDGs above.
        for (int p = tid; p < PN; p += THREADS) {
            int i = 0, rem = p;
            while (rem >= FN - 1 - i) { rem -= FN - 1 - i; i++; }
            int j = i + 1 + rem;
            tab[p] = (unsigned)(i * 4) | ((unsigned)(j * 4) << 16);
        }
    }
    __syncthreads();

    // ---- Phase 1: U = x @ Wi^T + b, V = x @ Wj^T  (f32x2, regs only) -----
    const int c  = tid & 63;
    const int fg = tid >> 6;

    unsigned long long au[10], av[10];
    #pragma unroll
    for (int k = 0; k < 10; k++) { au[k] = 0ull; av[k] = 0ull; }

    {
        const ulonglong2* xs2 = (const ulonglong2*)(smem + A_OFF);   // [f][16]
        const ulonglong2* Wi2 = (const ulonglong2*)(smem + B_OFF);   // [c][17]
        const ulonglong2* Wj2 = Wi2 + CN * 17;

        #pragma unroll
        for (int e4 = 0; e4 < 16; e4++) {
            ulonglong2 wi = Wi2[c * 17 + e4];
            ulonglong2 wj = Wj2[c * 17 + e4];
            #pragma unroll
            for (int k = 0; k < 10; k++) {
                ulonglong2 xv = xs2[(fg + 4 * k) * 16 + e4];  // f=39 row is zeros
                FMA_F32X2(au[k], xv.x, wi.x);
                FMA_F32X2(au[k], xv.y, wi.y);
                FMA_F32X2(av[k], xv.x, wj.x);
                FMA_F32X2(av[k], xv.y, wj.y);
            }
        }
    }
    __syncthreads();   // all xs/W reads done; safe to overlay

    // ---- Phase 1b: write Uc/Vc (transposed, stride 41) ------------------
    float* Uc = smem + A_OFF;                 // [c][41]
    float* Vc = smem + B_OFF;                 // [c][41]

    {
        const float bc = __ldg(bias + c);
        #pragma unroll
        for (int k = 0; k < 10; k++) {
            int f = fg + 4 * k;               // f<=39; f=39 lands in row pad
            float ulo = __uint_as_float((unsigned)au[k]);
            float uhi = __uint_as_float((unsigned)(au[k] >> 32));
            float vlo = __uint_as_float((unsigned)av[k]);
            float vhi = __uint_as_float((unsigned)(av[k] >> 32));
            Uc[c * 41 + f] = ulo + uhi + bc;  // bias folded into U
            Vc[c * 41 + f] = vlo + vhi;
        }
    }
    __syncthreads();

    // ---- Phase 2: expansion + relu, fused row pairs, register tab --------
    const int lane = tid & 31;
    const int wrp  = tid >> 5;
    float* outb = out + b * (long long)OUTB;

    #pragma unroll 1
    for (int k = 0; k < 4; k++) {
        const int r  = wrp * 4 + k;           // rows r and r+32 share p0
        const int p0 = (27 * r) & 31;

        // preload the 22-entry aligned tab window into registers
        unsigned tw[22];
        {
            const unsigned* tb = tab + p0 + lane;
            #pragma unroll
            for (int it = 0; it < 22; it++) tw[it] = tb[it * 32];
        }

        const char* bu0 = (const char*)(Uc + r * 41);
        const char* bv0 = (const char*)(Vc + r * 41);
        const char* bu1 = (const char*)(Uc + (r + 32) * 41);
        const char* bv1 = (const char*)(Vc + (r + 32) * 41);
        float* po0 = outb + r * PN;
        float* po1 = outb + (r + 32) * PN;

        // head: p in [0, p0), both rows
        if (lane < p0) {
            unsigned t = tab[lane];
            float u0 = *(const float*)(bu0 + (t & 0xFFFFu));
            float v0 = *(const float*)(bv0 + (t >> 16));
            float u1 = *(const float*)(bu1 + (t & 0xFFFFu));
            float v1 = *(const float*)(bv1 + (t >> 16));
            __stcs(po0 + lane, fmaxf(u0 + v0, 0.f));
            __stcs(po1 + lane, fmaxf(u1 + v1, 0.f));
        }

        // main: 22 warp-iterations, both rows per iteration (2 indep chains)
        float* q0 = po0 + p0;
        float* q1 = po1 + p0;
        #pragma unroll
        for (int it = 0; it < 22; it++) {
            unsigned t = tw[it];
            unsigned ui = t & 0xFFFFu, vi = t >> 16;
            float u0 = *(const float*)(bu0 + ui);
            float v0 = *(const float*)(bv0 + vi);
            float u1 = *(const float*)(bu1 + ui);
            float v1 = *(const float*)(bv1 + vi);
            __stcs(q0 + it * 32 + lane, fmaxf(u0 + v0, 0.f));
            __stcs(q1 + it * 32 + lane, fmaxf(u1 + v1, 0.f));
        }

        // tail: p in [p0+704, 741), both rows
        int p = p0 + 704 + lane;
        #pragma unroll
        for (int tt = 0; tt < 2; tt++) {
            if (p < PN) {
                unsigned t = tab[p];
                float u0 = *(const float*)(bu0 + (t & 0xFFFFu));
                float v0 = *(const float*)(bv0 + (t >> 16));
                float u1 = *(const float*)(bu1 + (t & 0xFFFFu));
                float v1 = *(const float*)(bv1 + (t >> 16));
                __stcs(po0 + p, fmaxf(u0 + v0, 0.f));
                __stcs(po1 + p, fmaxf(u1 + v1, 0.f));
            }
            p += 32;
        }
    }
}

extern "C" void kernel_launch(void* const* d_in, const int* in_sizes, int n_in,
                              void* d_out, int out_size)
{
    const float* x    = (const float*)d_in[0];
    const float* W    = (const float*)d_in[1];
    const float* bias = (const float*)d_in[2];
    float* out = (float*)d_out;

    const int B = in_sizes[0] / (FN * EN);   // 2048

    cudaFuncSetAttribute(interconv_kernel,
                         cudaFuncAttributeMaxDynamicSharedMemorySize, SMEM_BYTES);
    interconv_kernel<<<B, THREADS, SMEM_BYTES>>>(x, W, bias, out);
}